// round 7
// baseline (speedup 1.0000x reference)
#include <cuda_runtime.h>

#define BATCH 256
#define NROWS 256
#define MCOLS 256
#define DDIM  32
#define LOG2E 1.4426950408889634f
#define BIGF  (1e8f * LOG2E)       // boundary in scaled (D*log2e) domain

// ---- phase 1 (distance GEMM) ----
#define P1_TPB 64
#define P1_CB  32                  // columns per CTA
#define P1_R   4                   // rows per thread (64*4 = 256)

// ---- phase 2 (DP) ----
#define TPB   128                  // 4 warps, 2 DP rows per thread
#define NWARP 4
#define SLACK 16                   // startup ring cushion (columns)
#define PF    8                    // dist prefetch depth (iterations)
#define ITERS 288                  // 287 rounded up to PF multiple

__device__ float g_dist[(size_t)BATCH * MCOLS * NROWS];  // [b][j][i], scaled by log2e
__device__ float g_part[BATCH];
__device__ int   g_count;

typedef unsigned long long u64;

#define FMA_F32X2(d, a, b) \
    asm("fma.rn.f32x2 %0, %1, %2, %0;" : "+l"(d) : "l"(a), "l"(b))
#define PACK_F32X2(out, lo, hi) \
    asm("mov.b64 %0, {%1, %2};" : "=l"(out) : "f"(lo), "f"(hi))
#define UNPACK_F32X2(lo, hi, in) \
    asm("mov.b64 {%0, %1}, %2;" : "=f"(lo), "=f"(hi) : "l"(in))

__device__ __forceinline__ float ex2f(float x) {
    float r; asm("ex2.approx.f32 %0, %1;" : "=f"(r) : "f"(x)); return r;
}
__device__ __forceinline__ float lg2f(float x) {
    float r; asm("lg2.approx.f32 %0, %1;" : "=f"(r) : "f"(x)); return r;
}

// softmin in scaled (D*log2e) domain
__device__ __forceinline__ float softmin3s(float a, float b, float c) {
    float mn = fminf(fminf(a, b), c);
    float s  = ex2f(mn - a) + ex2f(mn - b) + ex2f(mn - c);
    return mn - lg2f(s);
}

// ============================================================
// Phase 1: dist[b][j][i] = max(|x_i|^2 + |y_j|^2 - 2 x.y, 0) * log2e
// x rows in registers (R=4), y in SMEM read as broadcast, f32x2 FMAs.
// ============================================================
__global__ __launch_bounds__(P1_TPB)
void dist_kernel(const float* __restrict__ X, const float* __restrict__ Y) {
    __shared__ ulonglong2 sy[8][P1_CB];   // [k-chunk][col] — broadcast reads
    __shared__ float      syn[P1_CB];     // |y_j|^2

    const int t  = threadIdx.x;
    const int b  = blockIdx.x;
    const int j0 = blockIdx.y * P1_CB;
    const float* xb = X + (size_t)b * NROWS * DDIM;
    const float* yb = Y + ((size_t)b * MCOLS + j0) * DDIM;

    const ulonglong2* yb16 = (const ulonglong2*)yb;
    for (int k = t; k < P1_CB * 8; k += P1_TPB) {
        int j = k >> 3, c = k & 7;
        sy[c][j] = yb16[k];
    }
    for (int j = t; j < P1_CB; j += P1_TPB) {
        const float4* row = (const float4*)(yb + j * DDIM);
        float acc = 0.f;
        #pragma unroll
        for (int c = 0; c < 8; c++) {
            float4 v = row[c];
            acc += v.x * v.x + v.y * v.y + v.z * v.z + v.w * v.w;
        }
        syn[j] = acc;
    }

    // this thread's 4 x-rows into registers (packed f32x2) + norms
    u64   ax[P1_R][16];
    float xn[P1_R];
    #pragma unroll
    for (int r = 0; r < P1_R; r++) {
        const float4* xr = (const float4*)(xb + (size_t)(P1_R * t + r) * DDIM);
        float acc = 0.f;
        #pragma unroll
        for (int c = 0; c < 8; c++) {
            float4 v = xr[c];
            PACK_F32X2(ax[r][2*c],   v.x, v.y);
            PACK_F32X2(ax[r][2*c+1], v.z, v.w);
            acc += v.x*v.x + v.y*v.y + v.z*v.z + v.w*v.w;
        }
        xn[r] = acc;
    }
    __syncthreads();

    float* dst = g_dist + ((size_t)b * MCOLS + j0) * NROWS + P1_R * t;
    #pragma unroll 2
    for (int j = 0; j < P1_CB; j++) {
        u64 a0 = 0ull, a1 = 0ull, a2 = 0ull, a3 = 0ull;
        #pragma unroll
        for (int c = 0; c < 8; c++) {
            ulonglong2 yv = sy[c][j];              // broadcast LDS.128
            FMA_F32X2(a0, ax[0][2*c],   yv.x);
            FMA_F32X2(a0, ax[0][2*c+1], yv.y);
            FMA_F32X2(a1, ax[1][2*c],   yv.x);
            FMA_F32X2(a1, ax[1][2*c+1], yv.y);
            FMA_F32X2(a2, ax[2][2*c],   yv.x);
            FMA_F32X2(a2, ax[2][2*c+1], yv.y);
            FMA_F32X2(a3, ax[3][2*c],   yv.x);
            FMA_F32X2(a3, ax[3][2*c+1], yv.y);
        }
        float yn = syn[j];
        float lo, hi;
        float4 o;
        UNPACK_F32X2(lo, hi, a0); o.x = fmaxf(fmaf(-2.f, lo + hi, xn[0] + yn), 0.f) * LOG2E;
        UNPACK_F32X2(lo, hi, a1); o.y = fmaxf(fmaf(-2.f, lo + hi, xn[1] + yn), 0.f) * LOG2E;
        UNPACK_F32X2(lo, hi, a2); o.z = fmaxf(fmaf(-2.f, lo + hi, xn[2] + yn), 0.f) * LOG2E;
        UNPACK_F32X2(lo, hi, a3); o.w = fmaxf(fmaf(-2.f, lo + hi, xn[3] + yn), 0.f) * LOG2E;
        *(float4*)(dst + (size_t)j * NROWS) = o;
    }
}

// ============================================================
// Phase 2: DP over precomputed dist, self-timed warp ring,
// dist prefetched PF iterations ahead through a register queue.
// ============================================================
__global__ __launch_bounds__(TPB)
void dp_kernel(float* __restrict__ out) {
    __shared__ u64   ring[NWARP - 1][MCOLS];   // tagged (col+1 | value bits)
    __shared__ float red[TPB];
    __shared__ int   islast;

    const int t    = threadIdx.x;
    const int lane = t & 31;
    const int w    = t >> 5;
    const int b    = blockIdx.x;

    for (int k = t; k < (NWARP - 1) * MCOLS; k += TPB)
        ((u64*)ring)[k] = 0ull;                // tag 0 = not ready
    __syncthreads();

    // this thread's 2 rows start at i = 2t; dist row-pair at column j is 8B at db + j*NROWS
    const float* db = g_dist + (size_t)b * MCOLS * NROWS + 2 * t;

    float left0 = BIGF, left1 = BIGF;
    float tl = (t == 0) ? 0.f : BIGF;

    volatile u64* myring = (w < NWARP - 1) ? &ring[w][0]     : 0;
    volatile u64* upring = (w > 0)         ? &ring[w - 1][0] : 0;

    // startup cushion
    if (w > 0) {
        u64 wd;
        do { wd = upring[SLACK]; } while ((unsigned)(wd >> 32) != (unsigned)(SLACK + 1));
    }

    // preload dist queue
    float2 q[PF];
    #pragma unroll
    for (int k = 0; k < PF; k++) {
        int col = (k - lane) & 255;
        q[k] = *(const float2*)(db + (size_t)col * NROWS);
    }

    for (int i0 = 0; i0 < ITERS; i0 += PF) {
        #pragma unroll
        for (int k = 0; k < PF; k++) {
            const int i = i0 + k;
            float up_sh = __shfl_up_sync(0xffffffffu, left1, 1);
            const int ii = (i < MCOLS) ? i : (MCOLS - 1);

            u64 word = 0ull;
            if (w > 0) word = upring[ii];       // optimistic early read (broadcast)

            float2 d2 = q[k];                   // dist for (rows 2t,2t+1, col i-lane)
            int nc = (i + PF - lane) & 255;     // refill PF ahead
            q[k] = *(const float2*)(db + (size_t)nc * NROWS);

            if (w > 0 && i < MCOLS) {           // tag check, rarely spins
                while ((unsigned)(word >> 32) != (unsigned)(ii + 1))
                    word = upring[ii];
            }
            float up0 = (lane == 0)
                      ? ((w == 0) ? BIGF : __uint_as_float((unsigned)word))
                      : up_sh;

            float v0  = d2.x + softmin3s(up0, left0, tl);
            float nv1 = d2.y + softmin3s(v0,  left1, left0);

            const int jj = i - lane;
            if (jj >= 0 && jj < MCOLS) {
                tl = up0; left0 = v0; left1 = nv1;
                if (lane == 31 && w < NWARP - 1)
                    myring[jj] = ((u64)(unsigned)(jj + 1) << 32) | (u64)__float_as_uint(nv1);
                if (w == NWARP - 1 && lane == 31 && jj == MCOLS - 1)
                    g_part[b] = nv1;            // scaled D[N][M]
            }
        }
    }

    // fused grid reduction (last CTA)
    __threadfence();
    __syncthreads();
    if (t == 0) islast = (atomicAdd(&g_count, 1) == BATCH - 1);
    __syncthreads();
    if (islast) {
        __threadfence();
        red[t] = g_part[t] + g_part[t + TPB];
        __syncthreads();
        #pragma unroll
        for (int off = TPB / 2; off > 0; off >>= 1) {
            if (t < off) red[t] += red[t + off];
            __syncthreads();
        }
        if (t == 0) {
            out[0] = red[0] * (1.0f / ((float)BATCH * LOG2E));
            g_count = 0;                        // reset for next graph replay
        }
    }
}

extern "C" void kernel_launch(void* const* d_in, const int* in_sizes, int n_in,
                              void* d_out, int out_size) {
    const float* x = (const float*)d_in[0];
    const float* y = (const float*)d_in[1];
    float* out = (float*)d_out;
    dist_kernel<<<dim3(BATCH, MCOLS / P1_CB), P1_TPB>>>(x, y);
    dp_kernel<<<BATCH, TPB>>>(out);
}